// round 7
// baseline (speedup 1.0000x reference)
#include <cuda_runtime.h>
#include <stdint.h>

#define GH 52
#define GW 52
#define NB 5
#define NBOX 13520                 // 52*52*5
#define ROWBITS 288                // padded bits per grid row (260 used)
#define RW 9                       // words per grid row
#define PWORDS 468                 // 52 * 9
#define PPOS   (PWORDS*32)
#define IOU_T  0.4f

#define CTAS   8                   // plain CTAs (NO cluster)
#define NMS_T  512
#define SLOTS  4                   // 16 warps * 4 = 64 >= 63 words max
#define LBASE  10                  // 1 pad word + 9 halo words above
#define LSZ    84                  // 10 + 63 own + 9 halo + 2 straddle pad

// Per-position predecessor masks (padded layout). x=dy-1, y=dy0, z=dy+1,
// 15 bits each (bit (dx+1)*5+bb). Padding positions stay zero forever.
__device__ ushort4  g_pm[PPOS];
// Boundary-row mirrors: [cta][0]=own top row, [1]=own bottom row.
__device__ uint32_t g_mir[CTAS][2][RW];
__device__ int      g_flag[CTAS];
__device__ int      g_cnt;         // software barrier arrivals (returns to 0)
__device__ int      g_gen;         // software barrier generation (monotone)

// ---------------------------------------------------------------------------
// Kernel 1: decode + per-row predecessor masks (R5/R6 version, proven exact)
// ---------------------------------------------------------------------------
__global__ void decode_kernel(const float* __restrict__ x, float* __restrict__ out)
{
    int id = blockIdx.x * blockDim.x + threadIdx.x;
    if (id >= 3 * NBOX) return;
    int dyI = id / NBOX;            // 0,1,2 -> dy = dyI-1
    int j   = id - dyI * NBOX;

    int cell = j / NB;
    int b    = j - cell * NB;
    int gy   = cell / GW;
    int gx   = cell - gy * GW;

    const float sx = 416.0f / GW;   // 8
    const float sy = 416.0f / GH;   // 8

    const float* p = x + j * 5;
    float c0 = p[0], c1 = p[1], c2 = p[2], c3 = p[3], sj = p[4];

    float cx = (c0 + (float)gx) * sx;
    float w  = c2 * sx;
    float cy = (c1 + (float)gy) * sy;
    float h  = c3 * sy;
    cy = 416.0f - cy;
    float jx1 = cx - w * 0.5f, jy1 = cy - h * 0.5f;
    float jx2 = cx + w * 0.5f, jy2 = cy + h * 0.5f;

    if (dyI == 1) {
        float* o = out + j * 5;
        o[0] = jx1; o[1] = jy1; o[2] = jx2; o[3] = jy2;
        // o[4] written by nms_kernel.
    }

    float aj = fmaxf(jx2 - jx1, 0.0f) * fmaxf(jy2 - jy1, 0.0f);

    unsigned mask = 0;
    int ny = gy + dyI - 1;
    if ((unsigned)ny < GH) {
        #pragma unroll
        for (int dxi = 0; dxi < 3; dxi++) {
            int nx = gx + dxi - 1;
            if ((unsigned)nx >= GW) continue;
            int ncell = ny * GW + nx;
            const float* cp = x + ncell * 25;
            float q[25];
            #pragma unroll
            for (int k = 0; k < 25; k++) q[k] = cp[k];

            #pragma unroll
            for (int bb = 0; bb < NB; bb++) {
                int i = ncell * NB + bb;
                float si = q[bb * 5 + 4];
                bool higher = (si > sj) || (si == sj && i < j);
                float d0 = q[bb * 5 + 0], d1 = q[bb * 5 + 1];
                float d2 = q[bb * 5 + 2], d3 = q[bb * 5 + 3];
                float icx = (d0 + (float)nx) * sx;
                float iw_ = d2 * sx;
                float icy = (d1 + (float)ny) * sy;
                float ih_ = d3 * sy;
                icy = 416.0f - icy;
                float ix1 = icx - iw_ * 0.5f, iy1 = icy - ih_ * 0.5f;
                float ix2 = icx + iw_ * 0.5f, iy2 = icy + ih_ * 0.5f;

                float iw = fmaxf(fminf(ix2, jx2) - fmaxf(ix1, jx1), 0.0f);
                float ih = fmaxf(fminf(iy2, jy2) - fmaxf(iy1, jy1), 0.0f);
                float inter = iw * ih;
                float ai  = fmaxf(ix2 - ix1, 0.0f) * fmaxf(iy2 - iy1, 0.0f);
                float uni = ai + aj - inter;
                float iou = (uni > 0.0f) ? inter / fmaxf(uni, 1e-12f) : 0.0f;
                bool on = (iou > IOU_T) && higher && (i != j);
                mask |= (on ? 1u : 0u) << (dxi * 5 + bb);
            }
        }
    }
    int pos = gy * ROWBITS + gx * 5 + b;
    ((unsigned short*)&g_pm[pos])[dyI] = (unsigned short)mask;
}

// ---------------------------------------------------------------------------
// Kernel 2: non-cluster multi-CTA fixpoint NMS.
// Phase A: bounded async free-run (racy; any state is a valid warm start).
// Phase B: verified Jacobi sweeps with software global barrier. Jacobi from
// ANY state converges in <= chain-depth sweeps; a globally clean sweep
// certifies the unique fixpoint == exact greedy NMS. Deterministic output.
// ---------------------------------------------------------------------------
__device__ __forceinline__ uint32_t gather15v(volatile const uint32_t* L, int bit)
{
    int wi = bit >> 5;
    uint32_t lo = L[wi], hi = L[wi + 1];
    return __funnelshift_r(lo, hi, bit) & 0x7FFFu;
}

// Sense-reversing software barrier (8 co-resident CTAs; gen is monotone so
// it is safe across graph replays).
__device__ __forceinline__ void gbar()
{
    __threadfence();
    __syncthreads();
    if (threadIdx.x == 0) {
        int g0 = *(volatile int*)&g_gen;
        int a  = atomicAdd(&g_cnt, 1);
        if (a == CTAS - 1) {
            atomicExch(&g_cnt, 0);
            __threadfence();
            atomicAdd(&g_gen, 1);
        } else {
            while (*(volatile int*)&g_gen == g0) { }
        }
        __threadfence();
    }
    __syncthreads();
}

__global__ void __launch_bounds__(NMS_T, 1)
nms_kernel(const float* __restrict__ x, float* __restrict__ out)
{
    __shared__ uint32_t L[LSZ];
    volatile uint32_t* Lv = L;

    int r    = blockIdx.x;
    int t    = threadIdx.x;
    int lane = t & 31;
    int wid  = t >> 5;

    int row0  = (r < 4) ? 7 * r : 28 + 6 * (r - 4);
    int nrows = (r < 4) ? 7 : 6;
    int ow0   = row0 * RW;
    int ownw  = nrows * RW;            // 63 or 54

    // Init local kept bitmap (valid bits 1; tail words 4 bits; pads/edges 0).
    for (int i = t; i < LSZ; i += NMS_T) {
        int gw = ow0 + i - LBASE;
        uint32_t v = 0;
        if (gw >= 0 && gw < PWORDS)
            v = ((gw % RW) == 8) ? 0xFu : 0xFFFFFFFFu;
        L[i] = v;
    }
    // Publish initial boundary mirrors (racy vs other CTAs: benign).
    if (t < RW) {
        int gw = ow0 + t;
        g_mir[r][0][t] = ((gw % RW) == 8) ? 0xFu : 0xFFFFFFFFu;
    } else if (t >= 32 && t < 32 + RW) {
        int q  = t - 32;
        int gw = ow0 + ownw - RW + q;
        g_mir[r][1][q] = ((gw % RW) == 8) ? 0xFu : 0xFFFFFFFFu;
    }

    // Slot precompute; masks + current word value cached in registers.
    bool act[SLOTS], topw[SLOTS], botw[SLOTS];
    int  lis[SLOTS], lbs[SLOTS], kArr[SLOTS], botq[SLOTS];
    uint32_t pmx[SLOTS], pmy[SLOTS], pmz[SLOTS], tailm[SLOTS], cur[SLOTS];
    #pragma unroll
    for (int s = 0; s < SLOTS; s++) {
        int k = wid * SLOTS + s;
        act[s] = (k < ownw);
        int kk = act[s] ? k : 0;
        int gw = ow0 + kk;
        int p  = gw * 32 + lane;
        ushort4 pm = __ldg(&g_pm[p]);
        pmx[s] = pm.x; pmy[s] = pm.y; pmz[s] = pm.z;
        int row = p / ROWBITS;
        int rem = p - row * ROWBITS;
        int b   = rem % 5;
        lis[s]  = LBASE + kk;
        lbs[s]  = lis[s] * 32 + lane - b - 5;
        tailm[s] = ((gw % RW) == 8) ? 0xFu : 0xFFFFFFFFu;
        cur[s]   = tailm[s];               // == initial word value
        kArr[s]  = kk;
        topw[s]  = act[s] && (kk < RW);
        botw[s]  = act[s] && (kk >= ownw - RW);
        botq[s]  = kk - (ownw - RW);
    }
    __syncthreads();

    // ---- Phase A: async free-run (no barriers; bounded loops) ----
    {
        int wlast   = (ownw - 1) / SLOTS;
        bool refTop = (wid == 0)     && (r > 0);
        bool refBot = (wid == wlast) && (r < CTAS - 1);
        int scap    = (wid == 0 || wid == wlast) ? 20 : 6;

        int streak = 0;
        for (int sw = 0; sw < 128 && streak < scap; sw++) {
            if (refTop && lane < RW)
                Lv[1 + lane] = *(volatile uint32_t*)&g_mir[r - 1][1][lane];
            if (refBot && lane < RW)
                Lv[LBASE + ownw + lane] = *(volatile uint32_t*)&g_mir[r + 1][0][lane];
            __syncwarp();

            bool ch = false;
            #pragma unroll
            for (int s = 0; s < SLOTS; s++) {
                if (!act[s]) continue;
                uint32_t gu = gather15v(Lv, lbs[s] - ROWBITS);
                uint32_t gm = gather15v(Lv, lbs[s]);
                uint32_t gd = gather15v(Lv, lbs[s] + ROWBITS);
                uint32_t sup = (gu & pmx[s]) | (gm & pmy[s]) | (gd & pmz[s]);
                uint32_t nw = __ballot_sync(0xFFFFFFFFu, sup == 0u) & tailm[s];
                if (nw != cur[s]) {
                    ch = true;
                    cur[s] = nw;
                    if (lane == 0) {
                        Lv[lis[s]] = nw;
                        if (topw[s]) *(volatile uint32_t*)&g_mir[r][0][kArr[s]] = nw;
                        if (botw[s]) *(volatile uint32_t*)&g_mir[r][1][botq[s]] = nw;
                    }
                }
            }
            streak = ch ? 0 : streak + 1;
        }
    }
    __syncthreads();

    // ---- Phase B: verified Jacobi sweeps with software global barrier ----
    for (int osw = 0; osw < NBOX; osw++) {
        // Publish current boundary rows.
        if (t < RW)
            g_mir[r][0][t] = L[LBASE + t];
        else if (t >= 32 && t < 32 + RW)
            g_mir[r][1][t - 32] = L[LBASE + ownw - RW + (t - 32)];
        gbar();                              // boundaries globally consistent

        // Read halos (exact neighbor state at the barrier snapshot).
        if (r > 0 && t < RW)
            L[1 + t] = *(volatile uint32_t*)&g_mir[r - 1][1][t];
        if (r < CTAS - 1 && t >= 32 && t < 32 + RW)
            L[LBASE + ownw + (t - 32)] = *(volatile uint32_t*)&g_mir[r + 1][0][t - 32];
        __syncthreads();

        int ch = 0;
        #pragma unroll
        for (int s = 0; s < SLOTS; s++) {
            if (!act[s]) continue;
            uint32_t gu = gather15v(Lv, lbs[s] - ROWBITS);
            uint32_t gm = gather15v(Lv, lbs[s]);
            uint32_t gd = gather15v(Lv, lbs[s] + ROWBITS);
            uint32_t sup = (gu & pmx[s]) | (gm & pmy[s]) | (gd & pmz[s]);
            uint32_t nw = __ballot_sync(0xFFFFFFFFu, sup == 0u) & tailm[s];
            if (nw != cur[s]) {
                ch = 1;
                cur[s] = nw;
                if (lane == 0) Lv[lis[s]] = nw;
            }
        }
        int anyc = __syncthreads_or(ch);
        if (t == 0) g_flag[r] = anyc;
        gbar();                              // flags + updates visible

        int d = (t < CTAS) ? *(volatile int*)&g_flag[t] : 0;
        int anyd = __syncthreads_or(d);
        if (!anyd) break;                    // identical decision in all CTAs
    }

    // Writeout: score if kept else 0, own words only.
    #pragma unroll
    for (int s = 0; s < SLOTS; s++) {
        if (!act[s]) continue;
        int gw  = ow0 + kArr[s];
        int p   = gw * 32 + lane;
        int row = p / ROWBITS;
        int rem = p - row * ROWBITS;
        if (rem < 260) {
            int j = row * 260 + rem;
            out[j * 5 + 4] = ((cur[s] >> lane) & 1u) ? __ldg(&x[j * 5 + 4]) : 0.0f;
        }
    }
}

// ---------------------------------------------------------------------------
extern "C" void kernel_launch(void* const* d_in, const int* in_sizes, int n_in,
                              void* d_out, int out_size)
{
    const float* x   = (const float*)d_in[0];
    float*       out = (float*)d_out;

    decode_kernel<<<(3 * NBOX + 255) / 256, 256>>>(x, out);
    nms_kernel<<<CTAS, NMS_T>>>(x, out);
}